// round 1
// baseline (speedup 1.0000x reference)
#include <cuda_runtime.h>

#define EPS_NORM 1e-12f

// Per-batch partial losses (scratch; no device allocation allowed).
__device__ float g_partials[4];

// Upper-triangular index into packed 8x8 symmetric accumulator.
__device__ __host__ __forceinline__ int triidx(int i, int j) {
    return i * 8 - (i * (i - 1)) / 2 + (j - i);
}

// One block per batch b. Computes M = sum_n v_n v_n^T where
// v_n = [p_n (normalized, 4), s_n (normalized, 4)] in R^8 (36 unique entries),
// then loss_b = ||PP^T||_F^2 - 2||PS^T||_F^2 + ||SS^T||_F^2 read off M's blocks.
__global__ void __launch_bounds__(256, 1)
gram_loss_kernel(const float* __restrict__ xp, const float* __restrict__ xs)
{
    constexpr int N = 4096;
    const int b = blockIdx.x;
    const int t = threadIdx.x;
    const float* pb = xp + b * 4 * N;
    const float* sb = xs + b * 4 * N;

    float acc[36];
#pragma unroll
    for (int i = 0; i < 36; ++i) acc[i] = 0.0f;

    // 4096 positions = 1024 float4 groups; 256 threads x 4 groups each.
#pragma unroll
    for (int j = 0; j < 4; ++j) {
        const int g = (t + j * 256) * 4;   // starting spatial index (float4-aligned)
        float pv[4][4], sv[4][4];
#pragma unroll
        for (int c = 0; c < 4; ++c) {
            float4 a = *reinterpret_cast<const float4*>(pb + c * N + g);
            pv[c][0] = a.x; pv[c][1] = a.y; pv[c][2] = a.z; pv[c][3] = a.w;
            float4 q = *reinterpret_cast<const float4*>(sb + c * N + g);
            sv[c][0] = q.x; sv[c][1] = q.y; sv[c][2] = q.z; sv[c][3] = q.w;
        }
#pragma unroll
        for (int k = 0; k < 4; ++k) {
            float sumsq_p = pv[0][k] * pv[0][k] + pv[1][k] * pv[1][k]
                          + pv[2][k] * pv[2][k] + pv[3][k] * pv[3][k];
            float sumsq_s = sv[0][k] * sv[0][k] + sv[1][k] * sv[1][k]
                          + sv[2][k] * sv[2][k] + sv[3][k] * sv[3][k];
            // torch F.normalize semantics: x / max(||x||, eps)
            float ip = 1.0f / fmaxf(sqrtf(sumsq_p), EPS_NORM);
            float is = 1.0f / fmaxf(sqrtf(sumsq_s), EPS_NORM);
            float v[8];
#pragma unroll
            for (int c = 0; c < 4; ++c) {
                v[c]     = pv[c][k] * ip;
                v[4 + c] = sv[c][k] * is;
            }
            int idx = 0;
#pragma unroll
            for (int i = 0; i < 8; ++i)
#pragma unroll
                for (int jj = i; jj < 8; ++jj)
                    acc[idx++] += v[i] * v[jj];
        }
    }

    // Intra-warp tree reduction of the 36 accumulators.
#pragma unroll
    for (int off = 16; off > 0; off >>= 1)
#pragma unroll
        for (int i = 0; i < 36; ++i)
            acc[i] += __shfl_down_sync(0xffffffffu, acc[i], off);

    __shared__ float red[8][36];
    const int warp = t >> 5;
    const int lane = t & 31;
    if (lane == 0) {
#pragma unroll
        for (int i = 0; i < 36; ++i) red[warp][i] = acc[i];
    }
    __syncthreads();

    if (t == 0) {
        float M[36];
#pragma unroll
        for (int i = 0; i < 36; ++i) {
            float s = red[0][i];
#pragma unroll
            for (int w = 1; w < 8; ++w) s += red[w][i];
            M[i] = s;
        }
        float loss = 0.0f;
        // ||P P^T||_F^2 : block (0..3, 0..3), symmetric -> off-diag weight 2
#pragma unroll
        for (int i = 0; i < 4; ++i)
#pragma unroll
            for (int jj = i; jj < 4; ++jj) {
                float m = M[triidx(i, jj)];
                loss += (i == jj ? 1.0f : 2.0f) * m * m;
            }
        // -2 ||P S^T||_F^2 : block (0..3, 4..7), full 4x4, weight 1 each
#pragma unroll
        for (int i = 0; i < 4; ++i)
#pragma unroll
            for (int jj = 4; jj < 8; ++jj) {
                float m = M[triidx(i, jj)];
                loss -= 2.0f * m * m;
            }
        // ||S S^T||_F^2 : block (4..7, 4..7)
#pragma unroll
        for (int i = 4; i < 8; ++i)
#pragma unroll
            for (int jj = i; jj < 8; ++jj) {
                float m = M[triidx(i, jj)];
                loss += (i == jj ? 1.0f : 2.0f) * m * m;
            }
        g_partials[b] = loss;
    }
}

__global__ void finalize_kernel(float* __restrict__ out)
{
    // Deterministic scalar sum of the 4 per-batch partials.
    float s = (g_partials[0] + g_partials[1]) + (g_partials[2] + g_partials[3]);
    out[0] = s * (1.0f / (4.0f * 4096.0f * 4096.0f));
}

extern "C" void kernel_launch(void* const* d_in, const int* in_sizes, int n_in,
                              void* d_out, int out_size)
{
    const float* xp = (const float*)d_in[0];  // x_pred [4,4,64,64] fp32
    const float* xs = (const float*)d_in[1];  // x_src  [4,4,64,64] fp32
    gram_loss_kernel<<<4, 256>>>(xp, xs);
    finalize_kernel<<<1, 1>>>((float*)d_out);
}

// round 2
// speedup vs baseline: 1.4250x; 1.4250x over previous
#include <cuda_runtime.h>

#define EPS_NORM 1e-12f

// Scratch (no device allocation allowed): per-block partial second-moment
// matrices and an arrival counter for the last-block-finalizes pattern.
__device__ float g_part[16][36];
__device__ unsigned int g_count = 0;

__device__ __forceinline__ int triidx(int i, int j) {
    return i * 8 - (i * (i - 1)) / 2 + (j - i);
}

// grid = 16 blocks (4 slices per batch), 256 threads.
// Each thread handles ONE float4 group (4 spatial positions) of one batch.
// For each position n: v_n = [p_n/||p_n||, s_n/||s_n||] in R^8.
// Block accumulates the 36 unique entries of sum_n v_n v_n^T for its slice.
// Last arriving block reduces all 16 partials and computes
//   loss = sum_b (||PP^T||_F^2 - 2||PS^T||_F^2 + ||SS^T||_F^2) / (B*N*N)
// using the exact identity sum_nm (a_n.a_m)(b_n.b_m) = ||A B^T||_F^2.
__global__ void __launch_bounds__(256, 1)
cosine_ssm_fused_kernel(const float* __restrict__ xp,
                        const float* __restrict__ xs,
                        float* __restrict__ out)
{
    constexpr int N = 4096;
    const int blk   = blockIdx.x;
    const int b     = blk >> 2;       // batch
    const int slice = blk & 3;        // quarter of the spatial dim
    const int t     = threadIdx.x;

    const float* pb = xp + b * 4 * N;
    const float* sb = xs + b * 4 * N;
    const int g = (slice * 1024) + t * 4;   // starting spatial index (float4-aligned)

    float pv[4][4], sv[4][4];
#pragma unroll
    for (int c = 0; c < 4; ++c) {
        float4 a = *reinterpret_cast<const float4*>(pb + c * N + g);
        pv[c][0] = a.x; pv[c][1] = a.y; pv[c][2] = a.z; pv[c][3] = a.w;
        float4 q = *reinterpret_cast<const float4*>(sb + c * N + g);
        sv[c][0] = q.x; sv[c][1] = q.y; sv[c][2] = q.z; sv[c][3] = q.w;
    }

    float acc[36];
#pragma unroll
    for (int i = 0; i < 36; ++i) acc[i] = 0.0f;

#pragma unroll
    for (int k = 0; k < 4; ++k) {
        float sumsq_p = pv[0][k] * pv[0][k] + pv[1][k] * pv[1][k]
                      + pv[2][k] * pv[2][k] + pv[3][k] * pv[3][k];
        float sumsq_s = sv[0][k] * sv[0][k] + sv[1][k] * sv[1][k]
                      + sv[2][k] * sv[2][k] + sv[3][k] * sv[3][k];
        // torch F.normalize semantics: x / max(||x||, eps)
        float ip = 1.0f / fmaxf(sqrtf(sumsq_p), EPS_NORM);
        float is = 1.0f / fmaxf(sqrtf(sumsq_s), EPS_NORM);
        float v[8];
#pragma unroll
        for (int c = 0; c < 4; ++c) {
            v[c]     = pv[c][k] * ip;
            v[4 + c] = sv[c][k] * is;
        }
        int idx = 0;
#pragma unroll
        for (int i = 0; i < 8; ++i)
#pragma unroll
            for (int jj = i; jj < 8; ++jj)
                acc[idx++] += v[i] * v[jj];
    }

    // Intra-warp tree reduction of the 36 accumulators.
#pragma unroll
    for (int off = 16; off > 0; off >>= 1)
#pragma unroll
        for (int i = 0; i < 36; ++i)
            acc[i] += __shfl_down_sync(0xffffffffu, acc[i], off);

    __shared__ float red[8][36];
    __shared__ float Msh[4][36];
    __shared__ bool  is_last;

    const int warp = t >> 5;
    const int lane = t & 31;
    if (lane == 0) {
#pragma unroll
        for (int i = 0; i < 36; ++i) red[warp][i] = acc[i];
    }
    __syncthreads();

    // Cross-warp reduce: 36 threads, one entry each -> per-block partial.
    if (t < 36) {
        float s = red[0][t];
#pragma unroll
        for (int w = 1; w < 8; ++w) s += red[w][t];
        g_part[blk][t] = s;
    }

    // Make partial visible, then arrive.
    __threadfence();
    __syncthreads();
    if (t == 0) {
        unsigned int old = atomicAdd(&g_count, 1u);
        is_last = (old == gridDim.x - 1);
    }
    __syncthreads();

    if (!is_last) return;

    // ---- last block: reduce 16 partials, evaluate loss, write scalar ----
    if (t < 36) {
#pragma unroll
        for (int bb = 0; bb < 4; ++bb) {
            volatile const float* p0 = &g_part[bb * 4 + 0][t];
            volatile const float* p1 = &g_part[bb * 4 + 1][t];
            volatile const float* p2 = &g_part[bb * 4 + 2][t];
            volatile const float* p3 = &g_part[bb * 4 + 3][t];
            Msh[bb][t] = (*p0 + *p1) + (*p2 + *p3);
        }
    }
    __syncthreads();

    if (t == 0) {
        float total = 0.0f;
#pragma unroll
        for (int bb = 0; bb < 4; ++bb) {
            const float* M = Msh[bb];
            float loss = 0.0f;
            // ||P P^T||_F^2 : block (0..3, 0..3), off-diag weight 2
#pragma unroll
            for (int i = 0; i < 4; ++i)
#pragma unroll
                for (int jj = i; jj < 4; ++jj) {
                    float m = M[triidx(i, jj)];
                    loss += (i == jj ? 1.0f : 2.0f) * m * m;
                }
            // -2 ||P S^T||_F^2 : block (0..3, 4..7)
#pragma unroll
            for (int i = 0; i < 4; ++i)
#pragma unroll
                for (int jj = 4; jj < 8; ++jj) {
                    float m = M[triidx(i, jj)];
                    loss -= 2.0f * m * m;
                }
            // ||S S^T||_F^2 : block (4..7, 4..7)
#pragma unroll
            for (int i = 4; i < 8; ++i)
#pragma unroll
                for (int jj = i; jj < 8; ++jj) {
                    float m = M[triidx(i, jj)];
                    loss += (i == jj ? 1.0f : 2.0f) * m * m;
                }
            total += loss;
        }
        out[0] = total * (1.0f / (4.0f * 4096.0f * 4096.0f));
        g_count = 0;   // reset for next (deterministic across graph replays)
    }
}

extern "C" void kernel_launch(void* const* d_in, const int* in_sizes, int n_in,
                              void* d_out, int out_size)
{
    const float* xp = (const float*)d_in[0];  // x_pred [4,4,64,64] fp32
    const float* xs = (const float*)d_in[1];  // x_src  [4,4,64,64] fp32
    cosine_ssm_fused_kernel<<<16, 256>>>(xp, xs, (float*)d_out);
}